// round 8
// baseline (speedup 1.0000x reference)
#include <cuda_runtime.h>

// MFELoss: softmax over C=4, masked squared-error reduction to a scalar.
// HBM-bound streaming reduction: 128 MiB preds (fp32) + 32 MiB target (int32).
// NOTE: JAX default config canonicalizes int64 -> int32, so target is int32.

#define NBLK 1184
#define NTHR 256

// Per-block partials: [0]=fne_sum, [1]=fpe_sum, [2]=fne_count
static __device__ float g_part[NBLK][3];

__device__ __forceinline__ void accum_row(float4 r, bool is_o, int oi,
                                          float& fne, float& fpe, float& cnt) {
    float m  = fmaxf(fmaxf(r.x, r.y), fmaxf(r.z, r.w));
    float e0 = __expf(r.x - m);
    float e1 = __expf(r.y - m);
    float e2 = __expf(r.z - m);
    float e3 = __expf(r.w - m);
    float inv = __frcp_rn(e0 + e1 + e2 + e3);
    float p0 = e0 * inv, p1 = e1 * inv, p2 = e2 * inv, p3 = e3 * inv;
    float s  = p0 + p1 + p2 + p3;              // numerically ~1, matches reference
    float po = (oi == 0) ? p0 : (oi == 1) ? p1 : (oi == 2) ? p2 : p3;
    float d1 = s - po;
    float d2 = po - 1.0f;
    float fne_i = 0.5f * (d1 * d1 + d2 * d2);
    float fpe_i = po * po;                     // 0.5*((-p)^2 + p^2)
    if (is_o) { fne += fne_i; cnt += 1.0f; }
    else      { fpe += fpe_i; }
}

__global__ void __launch_bounds__(NTHR)
mfe_reduce_kernel(const float4* __restrict__ preds,   // [B] rows of 4 floats
                  const int4*   __restrict__ tgt4,    // [B/4] quads of int32
                  const int*    __restrict__ oi_ptr,  // low 32 bits valid for i32/i64
                  int n_quads)                        // B/4
{
    const int oi = *oi_ptr;
    float fne = 0.0f, fpe = 0.0f, cnt = 0.0f;

    const int stride = gridDim.x * blockDim.x;
    for (int i = blockIdx.x * blockDim.x + threadIdx.x; i < n_quads; i += stride) {
        // Front-batch 5 independent loads (4x16B preds + 1x16B targets) for MLP.
        float4 r0 = preds[4 * i + 0];
        float4 r1 = preds[4 * i + 1];
        float4 r2 = preds[4 * i + 2];
        float4 r3 = preds[4 * i + 3];
        int4   t  = tgt4[i];
        accum_row(r0, t.x == oi, oi, fne, fpe, cnt);
        accum_row(r1, t.y == oi, oi, fne, fpe, cnt);
        accum_row(r2, t.z == oi, oi, fne, fpe, cnt);
        accum_row(r3, t.w == oi, oi, fne, fpe, cnt);
    }

    // Warp reduce
    #pragma unroll
    for (int off = 16; off > 0; off >>= 1) {
        fne += __shfl_down_sync(0xFFFFFFFFu, fne, off);
        fpe += __shfl_down_sync(0xFFFFFFFFu, fpe, off);
        cnt += __shfl_down_sync(0xFFFFFFFFu, cnt, off);
    }

    // Block reduce via shared
    __shared__ float s_fne[NTHR / 32];
    __shared__ float s_fpe[NTHR / 32];
    __shared__ float s_cnt[NTHR / 32];
    int lane = threadIdx.x & 31;
    int wid  = threadIdx.x >> 5;
    if (lane == 0) { s_fne[wid] = fne; s_fpe[wid] = fpe; s_cnt[wid] = cnt; }
    __syncthreads();
    if (wid == 0) {
        float f = (lane < NTHR / 32) ? s_fne[lane] : 0.0f;
        float p = (lane < NTHR / 32) ? s_fpe[lane] : 0.0f;
        float c = (lane < NTHR / 32) ? s_cnt[lane] : 0.0f;
        #pragma unroll
        for (int off = 4; off > 0; off >>= 1) {
            f += __shfl_down_sync(0xFFFFFFFFu, f, off);
            p += __shfl_down_sync(0xFFFFFFFFu, p, off);
            c += __shfl_down_sync(0xFFFFFFFFu, c, off);
        }
        if (lane == 0) {
            g_part[blockIdx.x][0] = f;
            g_part[blockIdx.x][1] = p;
            g_part[blockIdx.x][2] = c;
        }
    }
}

__global__ void __launch_bounds__(256)
mfe_finalize_kernel(float* __restrict__ out, float n_total)
{
    double fne = 0.0, fpe = 0.0, cnt = 0.0;
    for (int i = threadIdx.x; i < NBLK; i += 256) {
        fne += (double)g_part[i][0];
        fpe += (double)g_part[i][1];
        cnt += (double)g_part[i][2];
    }
    __shared__ double s_f[8], s_p[8], s_c[8];
    int lane = threadIdx.x & 31;
    int wid  = threadIdx.x >> 5;
    #pragma unroll
    for (int off = 16; off > 0; off >>= 1) {
        fne += __shfl_down_sync(0xFFFFFFFFu, fne, off);
        fpe += __shfl_down_sync(0xFFFFFFFFu, fpe, off);
        cnt += __shfl_down_sync(0xFFFFFFFFu, cnt, off);
    }
    if (lane == 0) { s_f[wid] = fne; s_p[wid] = fpe; s_c[wid] = cnt; }
    __syncthreads();
    if (threadIdx.x == 0) {
        double F = 0.0, P = 0.0, Cn = 0.0;
        for (int w = 0; w < 8; w++) { F += s_f[w]; P += s_p[w]; Cn += s_c[w]; }
        float fne_num = (float)Cn;
        float fpe_num = n_total - fne_num;
        out[0] = (float)(P / (double)fpe_num + F / (double)fne_num);
    }
}

extern "C" void kernel_launch(void* const* d_in, const int* in_sizes, int n_in,
                              void* d_out, int out_size)
{
    const float4* preds  = (const float4*)d_in[0];
    const int4*   tgt4   = (const int4*)d_in[1];
    const int*    oi_ptr = (const int*)d_in[2];
    float*        out    = (float*)d_out;

    int n_rows  = in_sizes[0] / 4;     // B
    int n_quads = n_rows / 4;

    mfe_reduce_kernel<<<NBLK, NTHR>>>(preds, tgt4, oi_ptr, n_quads);
    mfe_finalize_kernel<<<1, 256>>>(out, (float)n_rows);
}